// round 8
// baseline (speedup 1.0000x reference)
#include <cuda_runtime.h>
#include <cstdint>

// Problem constants
#define M_DIM 4096
#define N_DIM 32000
#define K_DIM 128
#define BM 128
#define BN 128
#define KP 132   // padded k-stride in smem words (conflict-free)

// Device scratch
__device__ float g_summed[M_DIM * K_DIM];   // 2 MB, TF32-rounded A
__device__ float g_W[N_DIM * K_DIM];        // 16.4 MB, TF32-rounded W
__device__ int   g_stride;                  // 1 = int32 indices, 2 = int64

__device__ __forceinline__ unsigned f2tf32(float f) {
    unsigned u;
    asm("cvt.rna.tf32.f32 %0, %1;" : "=r"(u) : "f"(f));
    return u;
}
__device__ __forceinline__ void cp16(uint32_t dst, const void* src) {
    asm volatile("cp.async.cg.shared.global [%0], [%1], 16;" :: "r"(dst), "l"(src));
}

// ---------------------------------------------------------------------------
// Detect int64 vs int32 index tensor (odd 32-bit words all zero => int64).
// ---------------------------------------------------------------------------
__global__ void detect_kernel(const int* __restrict__ x32) {
    __shared__ int any;
    if (threadIdx.x == 0) any = 0;
    __syncthreads();
    int i = 1 + 2 * threadIdx.x;
    int v = x32[i] | x32[i + 512] | x32[i + 1024] | x32[i + 1536];
    if (v) any = 1;   // benign race
    __syncthreads();
    if (threadIdx.x == 0) g_stride = any ? 1 : 2;
}

// ---------------------------------------------------------------------------
// Pre-round W to TF32 (lets the GEMM cp.async B tiles raw).
// ---------------------------------------------------------------------------
__global__ void round_w_kernel(const float4* __restrict__ W) {
    int i = blockIdx.x * 256 + threadIdx.x;
    float4 v = W[i];
    uint4 u;
    u.x = f2tf32(v.x); u.y = f2tf32(v.y);
    u.z = f2tf32(v.z); u.w = f2tf32(v.w);
    reinterpret_cast<uint4*>(g_W)[i] = u;
}

// ---------------------------------------------------------------------------
// CBOW gather-sum (padding_idx=0 skipped), TF32-rounded output.
// ---------------------------------------------------------------------------
__global__ void sum_emb_kernel(const int* __restrict__ x32,
                               const float4* __restrict__ emb) {
    int sample = blockIdx.x * 8 + (threadIdx.x >> 5);
    int v = threadIdx.x & 31;
    int stride = g_stride;
    float4 s = make_float4(0.f, 0.f, 0.f, 0.f);
#pragma unroll
    for (int c = 0; c < 8; c++) {
        int i = x32[(sample * 8 + c) * stride];
        if (i != 0) {
            float4 t = emb[i * 32 + v];
            s.x += t.x; s.y += t.y; s.z += t.z; s.w += t.w;
        }
    }
    uint4 u;
    u.x = f2tf32(s.x); u.y = f2tf32(s.y);
    u.z = f2tf32(s.z); u.w = f2tf32(s.w);
    reinterpret_cast<uint4*>(g_summed)[sample * 32 + v] = u;
}

// ---------------------------------------------------------------------------
// GEMM: out[M,N] = summed[M,K] @ W[N,K]^T + b
// CTA 128x128, 256 threads, 8 warps (4M x 2N), warp tile 32x64.
// ONLY B lives in smem (67.6 KB) -> 2 CTAs/SM (cross-CTA overlap of
// prologue/mainloop/epilogue). A fragments come straight from global
// (2 MB total, L2-resident, L1-cached) with one-kstep register prefetch.
// __launch_bounds__(256,2): acc 64 + frag ~32 regs fits the 128-reg budget.
// ---------------------------------------------------------------------------
__global__ void __launch_bounds__(256, 2)
gemm_kernel(const float* __restrict__ bias, float* __restrict__ out) {
    extern __shared__ unsigned Bs[];   // [128][132]
    const uint32_t sbase = (uint32_t)__cvta_generic_to_shared(Bs);

    const int tid = threadIdx.x;
    const int bm = blockIdx.y * BM;
    const int bn = blockIdx.x * BN;

    // ---- B tile fill via cp.async: 128 rows x 32 float4 ----
    const float4* Bg = reinterpret_cast<const float4*>(g_W) + bn * 32;
#pragma unroll
    for (int t = 0; t < 16; t++) {
        int idx = tid + t * 256;
        int row = idx >> 5, j = idx & 31;
        cp16(sbase + (row * KP + j * 4) * 4, Bg + row * 32 + j);
    }
    asm volatile("cp.async.commit_group;" ::: "memory");

    const int lane = tid & 31;
    const int warp = tid >> 5;
    const int wm = (warp & 3) * 32;    // 4 warps along M
    const int wn = (warp >> 2) * 64;   // 2 warps along N
    const int g  = lane >> 2;          // 0..7
    const int tg = lane & 3;           // 0..3

    // A row base for this thread (mi=0, row g); +16 rows = +2048, +8 = +1024
    const float* A0 = g_summed + (size_t)(bm + wm + g) * K_DIM;

    float acc[2][8][4];
#pragma unroll
    for (int mi = 0; mi < 2; mi++)
#pragma unroll
        for (int ni = 0; ni < 8; ni++)
#pragma unroll
            for (int r = 0; r < 4; r++) acc[mi][ni][r] = 0.f;

    unsigned af[2][2][4];
    auto lda = [&](int ks, unsigned a[2][4]) {
#pragma unroll
        for (int mi = 0; mi < 2; mi++) {
            const float* p = A0 + mi * 2048 + ks * 8 + tg;
            a[mi][0] = __float_as_uint(__ldg(p));
            a[mi][1] = __float_as_uint(__ldg(p + 1024));
            a[mi][2] = __float_as_uint(__ldg(p + 4));
            a[mi][3] = __float_as_uint(__ldg(p + 1028));
        }
    };

    lda(0, af[0]);                    // prefetch kstep 0 (overlaps cp.async)
    asm volatile("cp.async.wait_group 0;" ::: "memory");
    __syncthreads();

#pragma unroll 2
    for (int ks = 0; ks < 16; ks++) {
        const int cur = ks & 1;
        if (ks < 15) lda(ks + 1, af[cur ^ 1]);    // prefetch next kstep

        unsigned b[8][2];
        const int k0 = ks * 8;
#pragma unroll
        for (int ni = 0; ni < 8; ni++) {
            int c0 = (wn + ni * 8 + g) * KP + k0 + tg;
            b[ni][0] = Bs[c0];
            b[ni][1] = Bs[c0 + 4];
        }
#pragma unroll
        for (int mi = 0; mi < 2; mi++)
#pragma unroll
            for (int ni = 0; ni < 8; ni++)
                asm volatile(
                    "mma.sync.aligned.m16n8k8.row.col.f32.tf32.tf32.f32 "
                    "{%0,%1,%2,%3}, {%4,%5,%6,%7}, {%8,%9}, {%0,%1,%2,%3};"
                    : "+f"(acc[mi][ni][0]), "+f"(acc[mi][ni][1]),
                      "+f"(acc[mi][ni][2]), "+f"(acc[mi][ni][3])
                    : "r"(af[cur][mi][0]), "r"(af[cur][mi][1]),
                      "r"(af[cur][mi][2]), "r"(af[cur][mi][3]),
                      "r"(b[ni][0]), "r"(b[ni][1]));
    }

    // Epilogue: bias add + float2 stores. Tiles divide exactly.
#pragma unroll
    for (int ni = 0; ni < 8; ni++) {
        int col = bn + wn + ni * 8 + 2 * tg;
        float2 bb = *reinterpret_cast<const float2*>(bias + col);
#pragma unroll
        for (int mi = 0; mi < 2; mi++) {
            int row = bm + wm + mi * 16 + g;
            float2 v0 = make_float2(acc[mi][ni][0] + bb.x, acc[mi][ni][1] + bb.y);
            float2 v1 = make_float2(acc[mi][ni][2] + bb.x, acc[mi][ni][3] + bb.y);
            *reinterpret_cast<float2*>(out + (size_t)row * N_DIM + col) = v0;
            *reinterpret_cast<float2*>(out + (size_t)(row + 8) * N_DIM + col) = v1;
        }
    }
}

// ---------------------------------------------------------------------------
extern "C" void kernel_launch(void* const* d_in, const int* in_sizes, int n_in,
                              void* d_out, int out_size) {
    const int*   x    = (const int*)d_in[0];
    const float* emb  = (const float*)d_in[1];
    const float* W    = (const float*)d_in[2];
    const float* bias = (const float*)d_in[3];
    float* out = (float*)d_out;

    (void)in_sizes; (void)n_in; (void)out_size;

    static const int smem_bytes = BN * KP * 4;   // 67,584 B -> 2 CTAs/SM
    cudaFuncSetAttribute(gemm_kernel,
                         cudaFuncAttributeMaxDynamicSharedMemorySize,
                         smem_bytes);

    detect_kernel<<<1, 256>>>(x);
    round_w_kernel<<<N_DIM * K_DIM / 4 / 256, 256>>>((const float4*)W);
    sum_emb_kernel<<<M_DIM / 8, 256>>>(x, (const float4*)emb);

    dim3 grid(N_DIM / BN, M_DIM / BM);           // (250, 32)
    gemm_kernel<<<grid, 256, smem_bytes>>>(bias, out);
}

// round 10
// speedup vs baseline: 1.3404x; 1.3404x over previous
#include <cuda_runtime.h>
#include <cstdint>

// Problem constants
#define M_DIM 4096
#define N_DIM 32000
#define K_DIM 128
#define BM 128
#define BN 128
#define KP 132                    // padded k-stride (conflict-free LDS)
#define B_WORDS (BN * KP)         // 16896
#define A_WORDS (BM * KP)         // 16896
#define SMEM_WORDS (B_WORDS + 2 * A_WORDS)   // 50688 words = 202752 B

// Device scratch
__device__ float g_summed[M_DIM * K_DIM];   // 2 MB, TF32-rounded A
__device__ float g_W[N_DIM * K_DIM];        // 16.4 MB, TF32-rounded W
__device__ int   g_stride;                  // 1 = int32 indices, 2 = int64

__device__ __forceinline__ unsigned f2tf32(float f) {
    unsigned u;
    asm("cvt.rna.tf32.f32 %0, %1;" : "=r"(u) : "f"(f));
    return u;
}
__device__ __forceinline__ void cp16(uint32_t dst, const void* src) {
    asm volatile("cp.async.cg.shared.global [%0], [%1], 16;" :: "r"(dst), "l"(src));
}
__device__ __forceinline__ void cp_commit() {
    asm volatile("cp.async.commit_group;" ::: "memory");
}
__device__ __forceinline__ void cp_wait0() {
    asm volatile("cp.async.wait_group 0;" ::: "memory");
}

// ---------------------------------------------------------------------------
// Detect int64 vs int32 index tensor (odd 32-bit words all zero => int64).
// ---------------------------------------------------------------------------
__global__ void detect_kernel(const int* __restrict__ x32) {
    __shared__ int any;
    if (threadIdx.x == 0) any = 0;
    __syncthreads();
    int i = 1 + 2 * threadIdx.x;
    int v = x32[i] | x32[i + 512] | x32[i + 1024] | x32[i + 1536];
    if (v) any = 1;   // benign race
    __syncthreads();
    if (threadIdx.x == 0) g_stride = any ? 1 : 2;
}

// ---------------------------------------------------------------------------
// Pre-round W to TF32 (lets the GEMM cp.async B tiles raw).
// ---------------------------------------------------------------------------
__global__ void round_w_kernel(const float4* __restrict__ W) {
    int i = blockIdx.x * 256 + threadIdx.x;
    float4 v = W[i];
    uint4 u;
    u.x = f2tf32(v.x); u.y = f2tf32(v.y);
    u.z = f2tf32(v.z); u.w = f2tf32(v.w);
    reinterpret_cast<uint4*>(g_W)[i] = u;
}

// ---------------------------------------------------------------------------
// CBOW gather-sum (padding_idx=0 skipped), TF32-rounded output.
// ---------------------------------------------------------------------------
__global__ void sum_emb_kernel(const int* __restrict__ x32,
                               const float4* __restrict__ emb) {
    int sample = blockIdx.x * 8 + (threadIdx.x >> 5);
    int v = threadIdx.x & 31;
    int stride = g_stride;
    float4 s = make_float4(0.f, 0.f, 0.f, 0.f);
#pragma unroll
    for (int c = 0; c < 8; c++) {
        int i = x32[(sample * 8 + c) * stride];
        if (i != 0) {
            float4 t = emb[i * 32 + v];
            s.x += t.x; s.y += t.y; s.z += t.z; s.w += t.w;
        }
    }
    uint4 u;
    u.x = f2tf32(s.x); u.y = f2tf32(s.y);
    u.z = f2tf32(s.z); u.w = f2tf32(s.w);
    reinterpret_cast<uint4*>(g_summed)[sample * 32 + v] = u;
}

// ---------------------------------------------------------------------------
// A-tile fill (128x128 fp32-as-tf32) into buffer `buf` via cp.async.
// ---------------------------------------------------------------------------
__device__ __forceinline__ void fill_A(uint32_t sbase, int buf, int m_tile,
                                       int tid) {
    const float4* Ag = reinterpret_cast<const float4*>(g_summed) +
                       (size_t)m_tile * 4096;
    uint32_t abase = sbase + (B_WORDS + buf * A_WORDS) * 4;
#pragma unroll
    for (int t = 0; t < 16; t++) {
        int idx = tid + t * 256;
        int row = idx >> 5, j = idx & 31;
        cp16(abase + (row * KP + j * 4) * 4, Ag + idx);
    }
    cp_commit();
}

// ---------------------------------------------------------------------------
// GEMM: out[M,N] = summed[M,K] @ W[N,K]^T + b
// grid (250, 4): each CTA owns one 128-wide N stripe, loads B ONCE (67.6 KB),
// then loops 8 M-tiles with double-buffered A tiles (2 x 67.6 KB). A(it+1)
// streams via cp.async while the 16-kstep mainloop runs on A(it); epilogue
// stores straight from accumulator registers. 256 threads, 8 warps (4M x 2N),
// warp tile 32x64, frag registers double-buffered across k-steps.
// ---------------------------------------------------------------------------
__global__ void __launch_bounds__(256, 1)
gemm_kernel(const float* __restrict__ bias, float* __restrict__ out) {
    extern __shared__ unsigned smem[];
    unsigned* Bs = smem;                       // [128][132]
    const uint32_t sbase = (uint32_t)__cvta_generic_to_shared(smem);

    const int tid = threadIdx.x;
    const int gx = blockIdx.x;                 // N stripe (0..249)
    const int gy = blockIdx.y;                 // M group  (0..3)
    const int bn = gx * BN;

    // ---- B tile fill (once) + A tile 0, one cp.async group ----
    {
        const float4* Bg = reinterpret_cast<const float4*>(g_W) + bn * 32;
#pragma unroll
        for (int t = 0; t < 16; t++) {
            int idx = tid + t * 256;
            int row = idx >> 5, j = idx & 31;
            cp16(sbase + (row * KP + j * 4) * 4, Bg + row * 32 + j);
        }
    }
    fill_A(sbase, 0, gy * 8, tid);   // commits B + A0 together

    const int lane = tid & 31;
    const int warp = tid >> 5;
    const int wm = (warp & 3) * 32;    // 4 warps along M
    const int wn = (warp >> 2) * 64;   // 2 warps along N
    const int g  = lane >> 2;          // 0..7
    const int tg = lane & 3;           // 0..3

#pragma unroll 1
    for (int it = 0; it < 8; it++) {
        cp_wait0();
        __syncthreads();               // A(it) (+B on it=0) visible; buf^1 free

        if (it < 7) fill_A(sbase, (it + 1) & 1, gy * 8 + it + 1, tid);

        unsigned* As = smem + B_WORDS + (it & 1) * A_WORDS;

        float acc[2][8][4];
#pragma unroll
        for (int mi = 0; mi < 2; mi++)
#pragma unroll
            for (int ni = 0; ni < 8; ni++)
#pragma unroll
                for (int r = 0; r < 4; r++) acc[mi][ni][r] = 0.f;

        unsigned af[2][2][4], bf[2][8][2];
        auto load_frag = [&](int k0, unsigned a[2][4], unsigned b[8][2]) {
#pragma unroll
            for (int mi = 0; mi < 2; mi++) {
                int r0 = (wm + mi * 16 + g) * KP + k0 + tg;
                a[mi][0] = As[r0];
                a[mi][1] = As[r0 + 8 * KP];
                a[mi][2] = As[r0 + 4];
                a[mi][3] = As[r0 + 8 * KP + 4];
            }
#pragma unroll
            for (int ni = 0; ni < 8; ni++) {
                int c0 = (wn + ni * 8 + g) * KP + k0 + tg;
                b[ni][0] = Bs[c0];
                b[ni][1] = Bs[c0 + 4];
            }
        };

        load_frag(0, af[0], bf[0]);
#pragma unroll 2
        for (int ks = 0; ks < 16; ks++) {
            const int cur = ks & 1;
            if (ks < 15) load_frag((ks + 1) * 8, af[cur ^ 1], bf[cur ^ 1]);
#pragma unroll
            for (int mi = 0; mi < 2; mi++)
#pragma unroll
                for (int ni = 0; ni < 8; ni++)
                    asm volatile(
                        "mma.sync.aligned.m16n8k8.row.col.f32.tf32.tf32.f32 "
                        "{%0,%1,%2,%3}, {%4,%5,%6,%7}, {%8,%9}, {%0,%1,%2,%3};"
                        : "+f"(acc[mi][ni][0]), "+f"(acc[mi][ni][1]),
                          "+f"(acc[mi][ni][2]), "+f"(acc[mi][ni][3])
                        : "r"(af[cur][mi][0]), "r"(af[cur][mi][1]),
                          "r"(af[cur][mi][2]), "r"(af[cur][mi][3]),
                          "r"(bf[cur][ni][0]), "r"(bf[cur][ni][1]));
        }

        // Epilogue for this M-tile: bias add + float2 stores from registers.
        const int bm = (gy * 8 + it) * BM;
#pragma unroll
        for (int ni = 0; ni < 8; ni++) {
            int col = bn + wn + ni * 8 + 2 * tg;
            float2 bb = *reinterpret_cast<const float2*>(bias + col);
#pragma unroll
            for (int mi = 0; mi < 2; mi++) {
                int row = bm + wm + mi * 16 + g;
                float2 v0 = make_float2(acc[mi][ni][0] + bb.x,
                                        acc[mi][ni][1] + bb.y);
                float2 v1 = make_float2(acc[mi][ni][2] + bb.x,
                                        acc[mi][ni][3] + bb.y);
                *reinterpret_cast<float2*>(out + (size_t)row * N_DIM + col) = v0;
                *reinterpret_cast<float2*>(out + (size_t)(row + 8) * N_DIM + col) = v1;
            }
        }
    }
}

// ---------------------------------------------------------------------------
extern "C" void kernel_launch(void* const* d_in, const int* in_sizes, int n_in,
                              void* d_out, int out_size) {
    const int*   x    = (const int*)d_in[0];
    const float* emb  = (const float*)d_in[1];
    const float* W    = (const float*)d_in[2];
    const float* bias = (const float*)d_in[3];
    float* out = (float*)d_out;

    (void)in_sizes; (void)n_in; (void)out_size;

    static const int smem_bytes = SMEM_WORDS * 4;   // 202,752 B
    cudaFuncSetAttribute(gemm_kernel,
                         cudaFuncAttributeMaxDynamicSharedMemorySize,
                         smem_bytes);

    detect_kernel<<<1, 256>>>(x);
    round_w_kernel<<<N_DIM * K_DIM / 4 / 256, 256>>>((const float4*)W);
    sum_emb_kernel<<<M_DIM / 8, 256>>>(x, (const float4*)emb);

    dim3 grid(N_DIM / BN, 4);                       // (250, 4)
    gemm_kernel<<<grid, 256, smem_bytes>>>(bias, out);
}

// round 11
// speedup vs baseline: 1.3480x; 1.0057x over previous
#include <cuda_runtime.h>
#include <cstdint>

// Problem constants
#define M_DIM 4096
#define N_DIM 32000
#define K_DIM 128
#define BN 256                     // CTA N-stripe width (B resident)
#define KPB 132                    // B smem row stride, words (4g+tg banks, conflict-free)
#define KPA 68                     // A chunk row stride, words (64 k + pad)
#define B_WORDS (BN * KPB)         // 33792
#define A_BUF_WORDS (128 * KPA)    // 8704 (one 128-row x 64-k chunk)
#define SMEM_WORDS (B_WORDS + 2 * A_BUF_WORDS)   // 51200 words = 204800 B
#define TILES_PER_CTA 4
#define CHUNKS (TILES_PER_CTA * 2)

// Device scratch
__device__ float g_summed[M_DIM * K_DIM];   // 2 MB, TF32-rounded A
__device__ float g_W[N_DIM * K_DIM];        // 16.4 MB, TF32-rounded W
__device__ int   g_stride;                  // 1 = int32 indices, 2 = int64

__device__ __forceinline__ unsigned f2tf32(float f) {
    unsigned u;
    asm("cvt.rna.tf32.f32 %0, %1;" : "=r"(u) : "f"(f));
    return u;
}
__device__ __forceinline__ void cp16(uint32_t dst, const void* src) {
    asm volatile("cp.async.cg.shared.global [%0], [%1], 16;" :: "r"(dst), "l"(src));
}
__device__ __forceinline__ void cp_commit() {
    asm volatile("cp.async.commit_group;" ::: "memory");
}
template <int N> __device__ __forceinline__ void cp_wait() {
    asm volatile("cp.async.wait_group %0;" :: "n"(N));
}

// ---------------------------------------------------------------------------
// Detect int64 vs int32 index tensor (odd 32-bit words all zero => int64).
// ---------------------------------------------------------------------------
__global__ void detect_kernel(const int* __restrict__ x32) {
    __shared__ int any;
    if (threadIdx.x == 0) any = 0;
    __syncthreads();
    int i = 1 + 2 * threadIdx.x;
    int v = x32[i] | x32[i + 512] | x32[i + 1024] | x32[i + 1536];
    if (v) any = 1;   // benign race
    __syncthreads();
    if (threadIdx.x == 0) g_stride = any ? 1 : 2;
}

// ---------------------------------------------------------------------------
// Pre-round W to TF32 (lets the GEMM cp.async B tiles raw).
// ---------------------------------------------------------------------------
__global__ void round_w_kernel(const float4* __restrict__ W) {
    int i = blockIdx.x * 256 + threadIdx.x;
    float4 v = W[i];
    uint4 u;
    u.x = f2tf32(v.x); u.y = f2tf32(v.y);
    u.z = f2tf32(v.z); u.w = f2tf32(v.w);
    reinterpret_cast<uint4*>(g_W)[i] = u;
}

// ---------------------------------------------------------------------------
// CBOW gather-sum (padding_idx=0 skipped), TF32-rounded output.
// ---------------------------------------------------------------------------
__global__ void sum_emb_kernel(const int* __restrict__ x32,
                               const float4* __restrict__ emb) {
    int sample = blockIdx.x * 8 + (threadIdx.x >> 5);
    int v = threadIdx.x & 31;
    int stride = g_stride;
    float4 s = make_float4(0.f, 0.f, 0.f, 0.f);
#pragma unroll
    for (int c = 0; c < 8; c++) {
        int i = x32[(sample * 8 + c) * stride];
        if (i != 0) {
            float4 t = emb[i * 32 + v];
            s.x += t.x; s.y += t.y; s.z += t.z; s.w += t.w;
        }
    }
    uint4 u;
    u.x = f2tf32(s.x); u.y = f2tf32(s.y);
    u.z = f2tf32(s.z); u.w = f2tf32(s.w);
    reinterpret_cast<uint4*>(g_summed)[sample * 32 + v] = u;
}

// ---------------------------------------------------------------------------
// A K-chunk fill: 128 rows x 64 k-words (half of K) into buffer (idx&1).
// 2048 float4 / 512 threads = 4 each.
// ---------------------------------------------------------------------------
__device__ __forceinline__ void fill_chunk(uint32_t sbase, int gy, int idx,
                                           int tid) {
    const int m0 = gy * 512 + (idx >> 1) * 128;
    const int half = idx & 1;
    const float4* Ag = reinterpret_cast<const float4*>(g_summed);
    uint32_t abase = sbase + (B_WORDS + half * A_BUF_WORDS) * 4;
#pragma unroll
    for (int t = 0; t < 4; t++) {
        int i = tid + t * 512;
        int row = i >> 4, j = i & 15;
        cp16(abase + (row * KPA + j * 4) * 4,
             Ag + (size_t)(m0 + row) * 32 + half * 16 + j);
    }
    cp_commit();
}

// ---------------------------------------------------------------------------
// GEMM: out[M,N] = summed[M,K] @ W[N,K]^T + b
// grid (125, 8), 512 threads, 16 warps (4M x 4N), warp tile 32x64.
// B tile (256 x 128) resident in smem, loaded once. 4 M-tiles per CTA,
// streamed as 8 half-K chunks, double-buffered via cp.async. Fragment regs
// single-buffered (fits 128-reg cap at 512 threads); 4 warps/SMSP hide the
// per-kstep LDS->HMMA latency that capped tensor% at 40 with 8 warps.
// ---------------------------------------------------------------------------
__global__ void __launch_bounds__(512, 1)
gemm_kernel(const float* __restrict__ bias, float* __restrict__ out) {
    extern __shared__ unsigned smem[];
    unsigned* Bs = smem;                       // [256][132]
    const uint32_t sbase = (uint32_t)__cvta_generic_to_shared(smem);

    const int tid = threadIdx.x;
    const int gx = blockIdx.x;                 // N stripe (0..124)
    const int gy = blockIdx.y;                 // M group  (0..7), 512 rows each
    const int bn = gx * BN;

    // ---- prologue: B fill + chunk0 (group0), chunk1 (group1) ----
    {
        const float4* Bg = reinterpret_cast<const float4*>(g_W) + bn * 32;
#pragma unroll
        for (int t = 0; t < 16; t++) {
            int idx = tid + t * 512;
            int row = idx >> 5, j = idx & 31;
            cp16(sbase + (row * KPB + j * 4) * 4, Bg + idx);
        }
    }
    fill_chunk(sbase, gy, 0, tid);   // commits B + chunk0 together
    fill_chunk(sbase, gy, 1, tid);

    const int lane = tid & 31;
    const int warp = tid >> 5;
    const int wm = (warp & 3) * 32;    // 4 warps along M
    const int wn = (warp >> 2) * 64;   // 4 warps along N
    const int g  = lane >> 2;          // 0..7
    const int tg = lane & 3;           // 0..3

    float acc[2][8][4];
#pragma unroll
    for (int mi = 0; mi < 2; mi++)
#pragma unroll
        for (int ni = 0; ni < 8; ni++)
#pragma unroll
            for (int r = 0; r < 4; r++) acc[mi][ni][r] = 0.f;

#pragma unroll 1
    for (int idx = 0; idx < CHUNKS; idx++) {
        if (idx < CHUNKS - 1) cp_wait<1>(); else cp_wait<0>();
        __syncthreads();               // chunk idx (+B on idx=0) visible

        const unsigned* As = smem + B_WORDS + (idx & 1) * A_BUF_WORDS;
        const int kg = (idx & 1) * 64; // B k-offset for this chunk

#pragma unroll
        for (int ks = 0; ks < 8; ks++) {
            unsigned a[2][4], b[8][2];
#pragma unroll
            for (int mi = 0; mi < 2; mi++) {
                int r0 = (wm + mi * 16 + g) * KPA + ks * 8 + tg;
                a[mi][0] = As[r0];
                a[mi][1] = As[r0 + 8 * KPA];
                a[mi][2] = As[r0 + 4];
                a[mi][3] = As[r0 + 8 * KPA + 4];
            }
#pragma unroll
            for (int ni = 0; ni < 8; ni++) {
                int c0 = (wn + ni * 8 + g) * KPB + kg + ks * 8 + tg;
                b[ni][0] = Bs[c0];
                b[ni][1] = Bs[c0 + 4];
            }
#pragma unroll
            for (int mi = 0; mi < 2; mi++)
#pragma unroll
                for (int ni = 0; ni < 8; ni++)
                    asm volatile(
                        "mma.sync.aligned.m16n8k8.row.col.f32.tf32.tf32.f32 "
                        "{%0,%1,%2,%3}, {%4,%5,%6,%7}, {%8,%9}, {%0,%1,%2,%3};"
                        : "+f"(acc[mi][ni][0]), "+f"(acc[mi][ni][1]),
                          "+f"(acc[mi][ni][2]), "+f"(acc[mi][ni][3])
                        : "r"(a[mi][0]), "r"(a[mi][1]),
                          "r"(a[mi][2]), "r"(a[mi][3]),
                          "r"(b[ni][0]), "r"(b[ni][1]));
        }

        __syncthreads();               // all warps done reading buf (idx&1)
        if (idx + 2 < CHUNKS) fill_chunk(sbase, gy, idx + 2, tid);

        if (idx & 1) {
            // acc holds full K for tile idx>>1: bias add + store + re-zero
            const int bm = gy * 512 + (idx >> 1) * 128;
#pragma unroll
            for (int ni = 0; ni < 8; ni++) {
                int col = bn + wn + ni * 8 + 2 * tg;
                float2 bb = *reinterpret_cast<const float2*>(bias + col);
#pragma unroll
                for (int mi = 0; mi < 2; mi++) {
                    int row = bm + wm + mi * 16 + g;
                    float2 v0 = make_float2(acc[mi][ni][0] + bb.x,
                                            acc[mi][ni][1] + bb.y);
                    float2 v1 = make_float2(acc[mi][ni][2] + bb.x,
                                            acc[mi][ni][3] + bb.y);
                    *reinterpret_cast<float2*>(out + (size_t)row * N_DIM + col) = v0;
                    *reinterpret_cast<float2*>(out + (size_t)(row + 8) * N_DIM + col) = v1;
                    acc[mi][ni][0] = 0.f; acc[mi][ni][1] = 0.f;
                    acc[mi][ni][2] = 0.f; acc[mi][ni][3] = 0.f;
                }
            }
        }
    }
}

// ---------------------------------------------------------------------------
extern "C" void kernel_launch(void* const* d_in, const int* in_sizes, int n_in,
                              void* d_out, int out_size) {
    const int*   x    = (const int*)d_in[0];
    const float* emb  = (const float*)d_in[1];
    const float* W    = (const float*)d_in[2];
    const float* bias = (const float*)d_in[3];
    float* out = (float*)d_out;

    (void)in_sizes; (void)n_in; (void)out_size;

    static const int smem_bytes = SMEM_WORDS * 4;   // 204,800 B
    cudaFuncSetAttribute(gemm_kernel,
                         cudaFuncAttributeMaxDynamicSharedMemorySize,
                         smem_bytes);

    detect_kernel<<<1, 256>>>(x);
    round_w_kernel<<<N_DIM * K_DIM / 4 / 256, 256>>>((const float4*)W);
    sum_emb_kernel<<<M_DIM / 8, 256>>>(x, (const float4*)emb);

    dim3 grid(N_DIM / BN, 8);                       // (125, 8)
    gemm_kernel<<<grid, 512, smem_bytes>>>(bias, out);
}

// round 12
// speedup vs baseline: 1.9277x; 1.4301x over previous
#include <cuda_runtime.h>
#include <cuda_fp16.h>
#include <cstdint>

// Problem constants
#define M_DIM 4096
#define N_DIM 32000
#define K_DIM 128
#define BM 128
#define BN 256
#define KW 64    // K in 32-bit words (half2): 128 fp16 = 64 words
#define KP 68    // padded k-stride in words (68 % 32 == 4 -> conflict-free)

// Device scratch: fp16 copies, packed half2 per uint32
__device__ uint32_t g_Ah[M_DIM * KW];    // 1 MB
__device__ uint32_t g_Wh[N_DIM * KW];    // 8.2 MB
__device__ int g_stride;                 // 1 = int32 indices, 2 = int64

__device__ __forceinline__ uint32_t packh(float lo, float hi) {
    __half2 h = __floats2half2_rn(lo, hi);   // lo -> low half (first in memory)
    return *reinterpret_cast<uint32_t*>(&h);
}
__device__ __forceinline__ void cp16(uint32_t dst, const void* src) {
    asm volatile("cp.async.cg.shared.global [%0], [%1], 16;" :: "r"(dst), "l"(src));
}
template <int N> __device__ __forceinline__ void cp_wait() {
    asm volatile("cp.async.wait_group %0;" :: "n"(N));
}

// ---------------------------------------------------------------------------
// Detect int64 vs int32 index tensor (odd 32-bit words all zero => int64).
// ---------------------------------------------------------------------------
__global__ void detect_kernel(const int* __restrict__ x32) {
    __shared__ int any;
    if (threadIdx.x == 0) any = 0;
    __syncthreads();
    int i = 1 + 2 * threadIdx.x;
    int v = x32[i] | x32[i + 512] | x32[i + 1024] | x32[i + 1536];
    if (v) any = 1;   // benign race
    __syncthreads();
    if (threadIdx.x == 0) g_stride = any ? 1 : 2;
}

// ---------------------------------------------------------------------------
// W -> fp16 (packed half2).
// ---------------------------------------------------------------------------
__global__ void conv_w_kernel(const float4* __restrict__ W) {
    int i = blockIdx.x * 256 + threadIdx.x;   // 1,024,000 float4
    float4 v = W[i];
    g_Wh[i * 2]     = packh(v.x, v.y);
    g_Wh[i * 2 + 1] = packh(v.z, v.w);
}

// ---------------------------------------------------------------------------
// CBOW gather-sum (padding_idx=0 skipped), fp16 output (packed half2).
// ---------------------------------------------------------------------------
__global__ void sum_emb_kernel(const int* __restrict__ x32,
                               const float4* __restrict__ emb) {
    int sample = blockIdx.x * 8 + (threadIdx.x >> 5);
    int v = threadIdx.x & 31;
    int stride = g_stride;
    float4 s = make_float4(0.f, 0.f, 0.f, 0.f);
#pragma unroll
    for (int c = 0; c < 8; c++) {
        int i = x32[(sample * 8 + c) * stride];
        if (i != 0) {
            float4 t = emb[i * 32 + v];
            s.x += t.x; s.y += t.y; s.z += t.z; s.w += t.w;
        }
    }
    int base = sample * KW + v * 2;
    g_Ah[base]     = packh(s.x, s.y);
    g_Ah[base + 1] = packh(s.z, s.w);
}

// ---------------------------------------------------------------------------
// GEMM: out[M,N] = A[M,K] @ W[N,K]^T + b   (fp16 in, fp32 accumulate)
// CTA 128x256, 256 threads, 8 warps (2M x 4N), warp tile 64x64.
// mma.sync.m16n8k16.f16: HALF the MMA instructions of the tf32 path.
// K split into 4 chunks of 32 elems (16 words); all cp.async groups issued
// up front, compute chunk c overlaps loads of c+1..3. Fragment registers
// double-buffered across the 2 k-steps per chunk.
// Smem: A[128][68] + B[256][68] words = 104,448 B.
// ---------------------------------------------------------------------------
__global__ void __launch_bounds__(256, 1)
gemm_kernel(const float* __restrict__ bias, float* __restrict__ out) {
    extern __shared__ unsigned smem[];
    unsigned* As = smem;              // [128][68]
    unsigned* Bs = smem + BM * KP;    // [256][68]
    const uint32_t sbase = (uint32_t)__cvta_generic_to_shared(smem);

    const int tid = threadIdx.x;
    const int bm = blockIdx.y * BM;
    const int bn = blockIdx.x * BN;

    // ---- issue all 4 K-chunk load groups (A + B interleaved per chunk) ----
    const uint4* Ag = reinterpret_cast<const uint4*>(g_Ah) + bm * 16;
    const uint4* Bg = reinterpret_cast<const uint4*>(g_Wh) + bn * 16;
#pragma unroll
    for (int c = 0; c < 4; c++) {
#pragma unroll
        for (int t = 0; t < 2; t++) {              // A: 128 rows x 4 uint4
            int idx = tid + t * 256;
            int row = idx >> 2, j = idx & 3;
            cp16(sbase + (row * KP + c * 16 + j * 4) * 4,
                 Ag + row * 16 + c * 4 + j);
        }
#pragma unroll
        for (int t = 0; t < 4; t++) {              // B: 256 rows x 4 uint4
            int idx = tid + t * 256;
            int row = idx >> 2, j = idx & 3;
            cp16(sbase + (BM * KP + row * KP + c * 16 + j * 4) * 4,
                 Bg + row * 16 + c * 4 + j);
        }
        asm volatile("cp.async.commit_group;" ::: "memory");
    }

    const int lane = tid & 31;
    const int warp = tid >> 5;
    const int wm = (warp & 1) * 64;    // 2 warps along M
    const int wn = (warp >> 1) * 64;   // 4 warps along N
    const int g  = lane >> 2;          // 0..7
    const int tg = lane & 3;           // 0..3

    float acc[4][8][4];
#pragma unroll
    for (int mi = 0; mi < 4; mi++)
#pragma unroll
        for (int ni = 0; ni < 8; ni++)
#pragma unroll
            for (int r = 0; r < 4; r++) acc[mi][ni][r] = 0.f;

    unsigned af[2][4][4], bf[2][8][2];

    // fragment layout (m16n8k16.f16, row.col), word = 2 fp16:
    //  a0: rows g,    cols 2tg..2tg+1  -> word tg
    //  a1: rows g+8,  same cols
    //  a2: rows g,    cols 2tg+8..+9   -> word tg+4
    //  a3: rows g+8
    //  b0: col g, k 2tg..2tg+1 -> word tg ; b1: k 2tg+8..+9 -> word tg+4
    auto load_frag = [&](int k0w, unsigned a[4][4], unsigned b[8][2]) {
#pragma unroll
        for (int mi = 0; mi < 4; mi++) {
            int r0 = (wm + mi * 16 + g) * KP + k0w + tg;
            a[mi][0] = As[r0];
            a[mi][1] = As[r0 + 8 * KP];
            a[mi][2] = As[r0 + 4];
            a[mi][3] = As[r0 + 8 * KP + 4];
        }
#pragma unroll
        for (int ni = 0; ni < 8; ni++) {
            int c0 = (wn + ni * 8 + g) * KP + k0w + tg;
            b[ni][0] = Bs[c0];
            b[ni][1] = Bs[c0 + 4];
        }
    };
    auto mma_tile = [&](unsigned a[4][4], unsigned b[8][2]) {
#pragma unroll
        for (int mi = 0; mi < 4; mi++)
#pragma unroll
            for (int ni = 0; ni < 8; ni++)
                asm volatile(
                    "mma.sync.aligned.m16n8k16.row.col.f32.f16.f16.f32 "
                    "{%0,%1,%2,%3}, {%4,%5,%6,%7}, {%8,%9}, {%0,%1,%2,%3};"
                    : "+f"(acc[mi][ni][0]), "+f"(acc[mi][ni][1]),
                      "+f"(acc[mi][ni][2]), "+f"(acc[mi][ni][3])
                    : "r"(a[mi][0]), "r"(a[mi][1]), "r"(a[mi][2]), "r"(a[mi][3]),
                      "r"(b[ni][0]), "r"(b[ni][1]));
    };

#pragma unroll
    for (int c = 0; c < 4; c++) {
        if (c == 0)      cp_wait<3>();
        else if (c == 1) cp_wait<2>();
        else if (c == 2) cp_wait<1>();
        else             cp_wait<0>();
        __syncthreads();

        load_frag(c * 16, af[0], bf[0]);
#pragma unroll
        for (int q = 0; q < 2; q++) {              // 2 k-steps of k16 per chunk
            int cur = q & 1;
            if (q < 1) load_frag(c * 16 + 8, af[cur ^ 1], bf[cur ^ 1]);
            mma_tile(af[cur], bf[cur]);
        }
    }

    // Epilogue: bias add + float2 stores. Tiles divide exactly.
#pragma unroll
    for (int ni = 0; ni < 8; ni++) {
        int col = bn + wn + ni * 8 + 2 * tg;
        float2 bb = *reinterpret_cast<const float2*>(bias + col);
#pragma unroll
        for (int mi = 0; mi < 4; mi++) {
            int row = bm + wm + mi * 16 + g;
            float2 v0 = make_float2(acc[mi][ni][0] + bb.x, acc[mi][ni][1] + bb.y);
            float2 v1 = make_float2(acc[mi][ni][2] + bb.x, acc[mi][ni][3] + bb.y);
            *reinterpret_cast<float2*>(out + (size_t)row * N_DIM + col) = v0;
            *reinterpret_cast<float2*>(out + (size_t)(row + 8) * N_DIM + col) = v1;
        }
    }
}

// ---------------------------------------------------------------------------
extern "C" void kernel_launch(void* const* d_in, const int* in_sizes, int n_in,
                              void* d_out, int out_size) {
    const int*   x    = (const int*)d_in[0];
    const float* emb  = (const float*)d_in[1];
    const float* W    = (const float*)d_in[2];
    const float* bias = (const float*)d_in[3];
    float* out = (float*)d_out;

    (void)in_sizes; (void)n_in; (void)out_size;

    static const int smem_bytes = (BM + BN) * KP * 4;   // 104,448 B
    cudaFuncSetAttribute(gemm_kernel,
                         cudaFuncAttributeMaxDynamicSharedMemorySize,
                         smem_bytes);

    detect_kernel<<<1, 256>>>(x);
    conv_w_kernel<<<N_DIM * K_DIM / 4 / 256, 256>>>((const float4*)W);
    sum_emb_kernel<<<M_DIM / 8, 256>>>(x, (const float4*)emb);

    dim3 grid(N_DIM / BN, M_DIM / BM);                  // (125, 32)
    gemm_kernel<<<grid, 256, smem_bytes>>>(bias, out);
}

// round 14
// speedup vs baseline: 2.0275x; 1.0518x over previous
#include <cuda_runtime.h>
#include <cuda_fp16.h>
#include <cstdint>

// Problem constants
#define M_DIM 4096
#define N_DIM 32000
#define K_DIM 128
#define BM 128
#define BN 128
#define KW 64    // K in 32-bit words (half2): 128 fp16 = 64 words
#define KP 68    // padded k-stride in words (68 % 32 == 4 -> conflict-free)

// Device scratch: fp16 copies, packed half2 per uint32
__device__ uint32_t g_Ah[M_DIM * KW];    // 1 MB
__device__ uint32_t g_Wh[N_DIM * KW];    // 8.2 MB
__device__ int g_stride;                 // 1 = int32 indices, 2 = int64

__device__ __forceinline__ uint32_t packh(float lo, float hi) {
    __half2 h = __floats2half2_rn(lo, hi);   // lo -> low half (first in memory)
    return *reinterpret_cast<uint32_t*>(&h);
}
__device__ __forceinline__ void cp16(uint32_t dst, const void* src) {
    asm volatile("cp.async.cg.shared.global [%0], [%1], 16;" :: "r"(dst), "l"(src));
}
template <int N> __device__ __forceinline__ void cp_wait() {
    asm volatile("cp.async.wait_group %0;" :: "n"(N));
}

// ---------------------------------------------------------------------------
// Detect int64 vs int32 index tensor (odd 32-bit words all zero => int64).
// ---------------------------------------------------------------------------
__global__ void detect_kernel(const int* __restrict__ x32) {
    __shared__ int any;
    if (threadIdx.x == 0) any = 0;
    __syncthreads();
    int i = 1 + 2 * threadIdx.x;
    int v = x32[i] | x32[i + 512] | x32[i + 1024] | x32[i + 1536];
    if (v) any = 1;   // benign race
    __syncthreads();
    if (threadIdx.x == 0) g_stride = any ? 1 : 2;
}

// ---------------------------------------------------------------------------
// W -> fp16 (packed half2).
// ---------------------------------------------------------------------------
__global__ void conv_w_kernel(const float4* __restrict__ W) {
    int i = blockIdx.x * 256 + threadIdx.x;   // 1,024,000 float4
    float4 v = W[i];
    g_Wh[i * 2]     = packh(v.x, v.y);
    g_Wh[i * 2 + 1] = packh(v.z, v.w);
}

// ---------------------------------------------------------------------------
// CBOW gather-sum (padding_idx=0 skipped), fp16 output (packed half2).
// ---------------------------------------------------------------------------
__global__ void sum_emb_kernel(const int* __restrict__ x32,
                               const float4* __restrict__ emb) {
    int sample = blockIdx.x * 8 + (threadIdx.x >> 5);
    int v = threadIdx.x & 31;
    int stride = g_stride;
    float4 s = make_float4(0.f, 0.f, 0.f, 0.f);
#pragma unroll
    for (int c = 0; c < 8; c++) {
        int i = x32[(sample * 8 + c) * stride];
        if (i != 0) {
            float4 t = emb[i * 32 + v];
            s.x += t.x; s.y += t.y; s.z += t.z; s.w += t.w;
        }
    }
    int base = sample * KW + v * 2;
    g_Ah[base]     = packh(s.x, s.y);
    g_Ah[base + 1] = packh(s.z, s.w);
}

// ---------------------------------------------------------------------------
// GEMM: out[M,N] = A[M,K] @ W[N,K]^T + b   (fp16 in, fp32 accumulate)
// CTA 128x128, 256 threads, 8 warps (2M x 4N), warp tile 64x32.
// Smem A[128][68] + B[128][68] = 69,632 B -> 2 CTAs/SM; co-resident CTA's
// mainloop hides this CTA's prologue/epilogue. Frag regs single-buffered
// (4 warps/SMSP hide the LDS->HMMA chain), acc 64 regs; fits 128-reg cap.
// K split into 4 cp.async chunks, all issued up front.
// ---------------------------------------------------------------------------
__global__ void __launch_bounds__(256, 2)
gemm_kernel(const float* __restrict__ bias, float* __restrict__ out) {
    extern __shared__ unsigned smem[];
    unsigned* As = smem;              // [128][68]
    unsigned* Bs = smem + BM * KP;    // [128][68]
    const uint32_t sbase = (uint32_t)__cvta_generic_to_shared(smem);

    const int tid = threadIdx.x;
    const int bm = blockIdx.y * BM;
    const int bn = blockIdx.x * BN;

    // ---- issue all 4 K-chunk load groups (A + B per chunk) ----
    const uint4* Ag = reinterpret_cast<const uint4*>(g_Ah) + bm * 16;
    const uint4* Bg = reinterpret_cast<const uint4*>(g_Wh) + bn * 16;
#pragma unroll
    for (int c = 0; c < 4; c++) {
#pragma unroll
        for (int t = 0; t < 2; t++) {              // A: 128 rows x 4 uint4
            int idx = tid + t * 256;
            int row = idx >> 2, j = idx & 3;
            cp16(sbase + (row * KP + c * 16 + j * 4) * 4,
                 Ag + row * 16 + c * 4 + j);
        }
#pragma unroll
        for (int t = 0; t < 2; t++) {              // B: 128 rows x 4 uint4
            int idx = tid + t * 256;
            int row = idx >> 2, j = idx & 3;
            cp16(sbase + (BM * KP + row * KP + c * 16 + j * 4) * 4,
                 Bg + row * 16 + c * 4 + j);
        }
        asm volatile("cp.async.commit_group;" ::: "memory");
    }

    const int lane = tid & 31;
    const int warp = tid >> 5;
    const int wm = (warp & 1) * 64;    // 2 warps along M
    const int wn = (warp >> 1) * 32;   // 4 warps along N
    const int g  = lane >> 2;          // 0..7
    const int tg = lane & 3;           // 0..3

    float acc[4][4][4];
#pragma unroll
    for (int mi = 0; mi < 4; mi++)
#pragma unroll
        for (int ni = 0; ni < 4; ni++)
#pragma unroll
            for (int r = 0; r < 4; r++) acc[mi][ni][r] = 0.f;

#pragma unroll
    for (int c = 0; c < 4; c++) {
        if (c == 0)      cp_wait<3>();
        else if (c == 1) cp_wait<2>();
        else if (c == 2) cp_wait<1>();
        else             cp_wait<0>();
        __syncthreads();

#pragma unroll
        for (int q = 0; q < 2; q++) {              // 2 k-steps of k16 per chunk
            const int k0w = c * 16 + q * 8;
            unsigned a[4][4], b[4][2];
#pragma unroll
            for (int mi = 0; mi < 4; mi++) {
                int r0 = (wm + mi * 16 + g) * KP + k0w + tg;
                a[mi][0] = As[r0];
                a[mi][1] = As[r0 + 8 * KP];
                a[mi][2] = As[r0 + 4];
                a[mi][3] = As[r0 + 8 * KP + 4];
            }
#pragma unroll
            for (int ni = 0; ni < 4; ni++) {
                int c0 = (wn + ni * 8 + g) * KP + k0w + tg;
                b[ni][0] = Bs[c0];
                b[ni][1] = Bs[c0 + 4];
            }
#pragma unroll
            for (int mi = 0; mi < 4; mi++)
#pragma unroll
                for (int ni = 0; ni < 4; ni++)
                    asm volatile(
                        "mma.sync.aligned.m16n8k16.row.col.f32.f16.f16.f32 "
                        "{%0,%1,%2,%3}, {%4,%5,%6,%7}, {%8,%9}, {%0,%1,%2,%3};"
                        : "+f"(acc[mi][ni][0]), "+f"(acc[mi][ni][1]),
                          "+f"(acc[mi][ni][2]), "+f"(acc[mi][ni][3])
                        : "r"(a[mi][0]), "r"(a[mi][1]),
                          "r"(a[mi][2]), "r"(a[mi][3]),
                          "r"(b[ni][0]), "r"(b[ni][1]));
        }
    }

    // Epilogue: bias add + float2 stores. Tiles divide exactly.
#pragma unroll
    for (int ni = 0; ni < 4; ni++) {
        int col = bn + wn + ni * 8 + 2 * tg;
        float2 bb = *reinterpret_cast<const float2*>(bias + col);
#pragma unroll
        for (int mi = 0; mi < 4; mi++) {
            int row = bm + wm + mi * 16 + g;
            float2 v0 = make_float2(acc[mi][ni][0] + bb.x, acc[mi][ni][1] + bb.y);
            float2 v1 = make_float2(acc[mi][ni][2] + bb.x, acc[mi][ni][3] + bb.y);
            *reinterpret_cast<float2*>(out + (size_t)row * N_DIM + col) = v0;
            *reinterpret_cast<float2*>(out + (size_t)(row + 8) * N_DIM + col) = v1;
        }
    }
}

// ---------------------------------------------------------------------------
extern "C" void kernel_launch(void* const* d_in, const int* in_sizes, int n_in,
                              void* d_out, int out_size) {
    const int*   x    = (const int*)d_in[0];
    const float* emb  = (const float*)d_in[1];
    const float* W    = (const float*)d_in[2];
    const float* bias = (const float*)d_in[3];
    float* out = (float*)d_out;

    (void)in_sizes; (void)n_in; (void)out_size;

    static const int smem_bytes = (BM + BN) * KP * 4;   // 69,632 B -> 2 CTAs/SM
    cudaFuncSetAttribute(gemm_kernel,
                         cudaFuncAttributeMaxDynamicSharedMemorySize,
                         smem_bytes);

    detect_kernel<<<1, 256>>>(x);
    conv_w_kernel<<<N_DIM * K_DIM / 4 / 256, 256>>>((const float4*)W);
    sum_emb_kernel<<<M_DIM / 8, 256>>>(x, (const float4*)emb);

    dim3 grid(N_DIM / BN, M_DIM / BM);                  // (250, 32)
    gemm_kernel<<<grid, 256, smem_bytes>>>(bias, out);
}